// round 5
// baseline (speedup 1.0000x reference)
#include <cuda_runtime.h>
#include <math.h>

#define BB      256     // batch
#define TT      512     // time steps
#define DXc     100
#define DZc     100
#define DH1c    10
#define DH2c    10
#define DDZc    20
#define DDXc    20
#define OUTD    500
#define NTHR    224

// ---------------- packed f32x2 helpers (FFMA2) ----------------
__device__ __forceinline__ unsigned long long pack2(float lo, float hi) {
    unsigned long long u;
    asm("mov.b64 %0,{%1,%2};" : "=l"(u) : "f"(lo), "f"(hi));
    return u;
}
__device__ __forceinline__ unsigned long long ffma2(unsigned long long a,
                                                    unsigned long long b,
                                                    unsigned long long c) {
    unsigned long long d;
    asm("fma.rn.f32x2 %0,%1,%2,%3;" : "=l"(d) : "l"(a), "l"(b), "l"(c));
    return d;
}
__device__ __forceinline__ float red2(unsigned long long u) {
    float lo, hi;
    asm("mov.b64 {%0,%1},%2;" : "=f"(lo), "=f"(hi) : "l"(u));
    return lo + hi;
}

// dot over NP float2-pairs: weights in registers (packed), vector in shared
template <int NP>
__device__ __forceinline__ float dot_rw(const unsigned long long* __restrict__ w,
                                        const float* __restrict__ v) {
    const float2* v2 = reinterpret_cast<const float2*>(v);
    unsigned long long a0 = 0ull, a1 = 0ull;
#pragma unroll
    for (int p = 0; p < NP; p += 2) {
        float2 t0 = v2[p];
        a0 = ffma2(w[p], pack2(t0.x, t0.y), a0);
        if (p + 1 < NP) {
            float2 t1 = v2[p + 1];
            a1 = ffma2(w[p + 1], pack2(t1.x, t1.y), a1);
        }
    }
    return red2(a0) + red2(a1);
}

// dot over NP float2-pairs: both operands in shared memory
template <int NP>
__device__ __forceinline__ float dot_ss(const float* __restrict__ w,
                                        const float* __restrict__ v) {
    const float2* w2 = reinterpret_cast<const float2*>(w);
    const float2* v2 = reinterpret_cast<const float2*>(v);
    unsigned long long a0 = 0ull, a1 = 0ull;
#pragma unroll
    for (int p = 0; p < NP; p += 2) {
        float2 aw = w2[p], av = v2[p];
        a0 = ffma2(pack2(aw.x, aw.y), pack2(av.x, av.y), a0);
        if (p + 1 < NP) {
            float2 bw = w2[p + 1], bv = v2[p + 1];
            a1 = ffma2(pack2(bw.x, bw.y), pack2(bv.x, bv.y), a1);
        }
    }
    return red2(a0) + red2(a1);
}

// precise sigmoid (recurrent path), fast softplus (output path)
__device__ __forceinline__ float sigm(float x) { return 1.0f / (1.0f + expf(-x)); }
__device__ __forceinline__ float softplus_f(float x) {
    return fmaxf(x, 0.0f) + log1pf(__expf(-fabsf(x)));
}

__global__ void __launch_bounds__(NTHR, 1)
arfssm_kernel(const float* __restrict__ x, const float* __restrict__ eps,
              const float* __restrict__ W_ih1, const float* __restrict__ W_hh1,
              const float* __restrict__ b_ih1, const float* __restrict__ b_hh1,
              const float* __restrict__ W_ih2, const float* __restrict__ W_hh2,
              const float* __restrict__ b_ih2, const float* __restrict__ b_hh2,
              const float* __restrict__ dzW1, const float* __restrict__ dzb1,
              const float* __restrict__ dzWloc, const float* __restrict__ dzbloc,
              const float* __restrict__ dzWsc, const float* __restrict__ dzbsc,
              const float* __restrict__ dxW1, const float* __restrict__ dxb1,
              const float* __restrict__ dxWloc, const float* __restrict__ dxbloc,
              const float* __restrict__ dxWsc, const float* __restrict__ dxbsc,
              const float* __restrict__ h1_0, const float* __restrict__ h2_0,
              float* __restrict__ out) {
    __shared__ __align__(16) float s_Wih2[30 * DXc];     // 3000
    __shared__ __align__(16) float s_Whh1[30 * DH1c];    // 300
    __shared__ __align__(16) float s_Whh2[30 * DH2c];    // 300
    __shared__ float s_bih1[30], s_bhh1[30], s_bih2[30], s_bhh2[30];
    __shared__ __align__(16) float s_dzW1[DDZc * DH1c];  // 200
    __shared__ float s_dzb1[DDZc];
    __shared__ __align__(16) float s_dxW1[DDXc * (DH1c + DH2c)];  // 400
    __shared__ float s_dxb1[DDXc];

    __shared__ __align__(16) float s_x[2][DXc];
    __shared__ __align__(16) float s_z[2][DZc];
    __shared__ __align__(16) float s_hdz[2][DDZc];
    __shared__ __align__(16) float s_hdx[2][DDXc];
    __shared__ float s_h1[2][DH1c], s_h1n[2][DH1c];
    __shared__ float s_h2[2][DH2c], s_h2n[2][DH2c];
    __shared__ float s_g1[2][30], s_gh1[2][30];
    __shared__ float s_g2[2][30], s_gh2[2][30];

    const int tid = threadIdx.x;
    const int b0 = blockIdx.x * 2;

    // ---- cooperative shared weight load ----
    for (int i = tid; i < 30 * DXc; i += NTHR) s_Wih2[i] = W_ih2[i];
    for (int i = tid; i < 30 * DH1c; i += NTHR) s_Whh1[i] = W_hh1[i];
    for (int i = tid; i < 30 * DH2c; i += NTHR) s_Whh2[i] = W_hh2[i];
    if (tid < 30) {
        s_bih1[tid] = b_ih1[tid]; s_bhh1[tid] = b_hh1[tid];
        s_bih2[tid] = b_ih2[tid]; s_bhh2[tid] = b_hh2[tid];
    }
    for (int i = tid; i < DDZc * DH1c; i += NTHR) s_dzW1[i] = dzW1[i];
    if (tid < DDZc) s_dzb1[tid] = dzb1[tid];
    for (int i = tid; i < DDXc * (DH1c + DH2c); i += NTHR) s_dxW1[i] = dxW1[i];
    if (tid < DDXc) s_dxb1[tid] = dxb1[tid];
    if (tid < DH1c) { s_h1[0][tid] = h1_0[tid]; s_h1[1][tid] = h1_0[tid]; }
    if (tid < DH2c) { s_h2[0][tid] = h2_0[tid]; s_h2[1][tid] = h2_0[tid]; }

    // ---- register-resident weights ----
    unsigned long long wzl[10], wzs[10], wxl[10], wxs[10];
    float bzl = 0.f, bzs = 0.f, bxl = 0.f, bxs = 0.f;
    if (tid < 100) {
        const float2* p;
        p = reinterpret_cast<const float2*>(dzWloc + tid * DDZc);
#pragma unroll
        for (int q = 0; q < 10; q++) { float2 t = p[q]; wzl[q] = pack2(t.x, t.y); }
        p = reinterpret_cast<const float2*>(dzWsc + tid * DDZc);
#pragma unroll
        for (int q = 0; q < 10; q++) { float2 t = p[q]; wzs[q] = pack2(t.x, t.y); }
        p = reinterpret_cast<const float2*>(dxWloc + tid * DDXc);
#pragma unroll
        for (int q = 0; q < 10; q++) { float2 t = p[q]; wxl[q] = pack2(t.x, t.y); }
        p = reinterpret_cast<const float2*>(dxWsc + tid * DDXc);
#pragma unroll
        for (int q = 0; q < 10; q++) { float2 t = p[q]; wxs[q] = pack2(t.x, t.y); }
        bzl = dzbloc[tid]; bzs = dzbsc[tid]; bxl = dxbloc[tid]; bxs = dxbsc[tid];
    }
    // gi1 threads: tids 128..187, split-2 over K=100
    unsigned long long wa[25];
    int gj = 0, ghalf = 0;
    if (tid >= 128 && tid < 188) {
        int u = tid - 128;
        gj = u >> 1; ghalf = u & 1;
        const float2* p = reinterpret_cast<const float2*>(W_ih1 + gj * DXc + ghalf * 50);
#pragma unroll
        for (int q = 0; q < 25; q++) { float2 t = p[q]; wa[q] = pack2(t.x, t.y); }
    }

    // ---- prefetch t=0 ----
    float xr[2] = {0.f, 0.f}, er[2] = {0.f, 0.f};
    if (tid < 100) {
#pragma unroll
        for (int bb = 0; bb < 2; bb++) {
            size_t base = ((size_t)(b0 + bb) * TT) * DXc + tid;
            xr[bb] = x[base];
            er[bb] = eps[base];
        }
    }
    __syncthreads();

    for (int t = 0; t < TT; t++) {
        // ===== S0: stash x, dz-hidden, gh1, gh2, prefetch x(t+1) =====
        if (tid < 100) { s_x[0][tid] = xr[0]; s_x[1][tid] = xr[1]; }
        if (tid < 40) {                       // hdz: 2 batches x 20
            int bb = tid / 20, j = tid % 20;
            float acc = s_dzb1[j];
#pragma unroll
            for (int k = 0; k < DH1c; k++) acc = fmaf(s_dzW1[j * DH1c + k], s_h1[bb][k], acc);
            s_hdz[bb][j] = fmaxf(acc, 0.0f);
        }
        if (tid >= 64 && tid < 124) {         // gh1: 2 x 30
            int u = tid - 64, bb = u / 30, j = u % 30;
            float acc = s_bhh1[j];
#pragma unroll
            for (int k = 0; k < DH1c; k++) acc = fmaf(s_Whh1[j * DH1c + k], s_h1[bb][k], acc);
            s_gh1[bb][j] = acc;
        }
        if (tid >= 128 && tid < 188) {        // gh2: 2 x 30
            int u = tid - 128, bb = u / 30, j = u % 30;
            float acc = s_bhh2[j];
#pragma unroll
            for (int k = 0; k < DH2c; k++) acc = fmaf(s_Whh2[j * DH2c + k], s_h2[bb][k], acc);
            s_gh2[bb][j] = acc;
        }
        if (tid < 100 && t + 1 < TT) {
#pragma unroll
            for (int bb = 0; bb < 2; bb++)
                xr[bb] = x[((size_t)(b0 + bb) * TT + (t + 1)) * DXc + tid];
        }
        __syncthreads();

        // ===== S1: z head (tid<100); gi2 batch0 (warp6) =====
        if (tid < 100) {
#pragma unroll
            for (int bb = 0; bb < 2; bb++) {
                float zl = dot_rw<10>(wzl, &s_hdz[bb][0]) + bzl;
                float zs = softplus_f(dot_rw<10>(wzs, &s_hdz[bb][0]) + bzs);
                float zt = fmaf(zs, er[bb], zl);
                s_z[bb][tid] = zt;
                float* o = out + ((size_t)(b0 + bb) * TT + t) * OUTD;
                o[200 + tid] = zl;
                o[300 + tid] = zs;
                o[400 + tid] = zt;
            }
            if (t + 1 < TT) {
#pragma unroll
                for (int bb = 0; bb < 2; bb++)
                    er[bb] = eps[((size_t)(b0 + bb) * TT + (t + 1)) * DXc + tid];
            }
        }
        if (tid >= 192 && tid < 222) {        // gi2[b=0]
            int j = tid - 192;
            s_g2[0][j] = s_bih2[j] + dot_ss<50>(&s_Wih2[j * DXc], &s_x[0][0]);
        }
        __syncthreads();

        // ===== S2: gi1 (warps 4-5, split-2 + shfl); gi2 batch1 (warp6) =====
        if (tid >= 128 && tid < 188) {
            unsigned mask = (tid < 160) ? 0xFFFFFFFFu : 0x0FFFFFFFu;
#pragma unroll
            for (int bb = 0; bb < 2; bb++) {
                float v = dot_rw<25>(wa, &s_z[bb][ghalf * 50]);
                v += __shfl_xor_sync(mask, v, 1);
                if (ghalf == 0) s_g1[bb][gj] = v + s_bih1[gj];
            }
        }
        if (tid >= 192 && tid < 222) {        // gi2[b=1]
            int j = tid - 192;
            s_g2[1][j] = s_bih2[j] + dot_ss<50>(&s_Wih2[j * DXc], &s_x[1][0]);
        }
        __syncthreads();

        // ===== S3: GRU1 combine + dx-hidden (warp0: b0, warp1: b1); GRU2 combine (warp2) =====
        {
            int warp = tid >> 5, lane = tid & 31;
            if (warp < 2) {
                int bb = warp;
                float h1n_val = 0.0f;
                if (lane < DH1c) {
                    float r = sigm(s_g1[bb][lane] + s_gh1[bb][lane]);
                    float uu = sigm(s_g1[bb][10 + lane] + s_gh1[bb][10 + lane]);
                    float n = tanhf(fmaf(r, s_gh1[bb][20 + lane], s_g1[bb][20 + lane]));
                    h1n_val = fmaf(uu, s_h1[bb][lane] - n, n);
                    s_h1n[bb][lane] = h1n_val;
                }
                float hk[10];
#pragma unroll
                for (int k = 0; k < 10; k++) hk[k] = __shfl_sync(0xFFFFFFFFu, h1n_val, k);
                if (lane < DDXc) {
                    float acc = s_dxb1[lane];
#pragma unroll
                    for (int k = 0; k < 10; k++) acc = fmaf(s_dxW1[lane * 20 + k], hk[k], acc);
#pragma unroll
                    for (int k = 0; k < 10; k++) acc = fmaf(s_dxW1[lane * 20 + 10 + k], s_h2[bb][k], acc);
                    s_hdx[bb][lane] = fmaxf(acc, 0.0f);
                }
            } else if (warp == 2 && lane < 20) {
                int bb = lane / 10, j = lane % 10;
                float r = sigm(s_g2[bb][j] + s_gh2[bb][j]);
                float uu = sigm(s_g2[bb][10 + j] + s_gh2[bb][10 + j]);
                float n = tanhf(fmaf(r, s_gh2[bb][20 + j], s_g2[bb][20 + j]));
                s_h2n[bb][j] = fmaf(uu, s_h2[bb][j] - n, n);
            }
        }
        __syncthreads();

        // ===== S4: x head (tid<100); state carry (tids 128..167) =====
        if (tid < 100) {
#pragma unroll
            for (int bb = 0; bb < 2; bb++) {
                float xl = dot_rw<10>(wxl, &s_hdx[bb][0]) + bxl;
                float xs = softplus_f(dot_rw<10>(wxs, &s_hdx[bb][0]) + bxs);
                float* o = out + ((size_t)(b0 + bb) * TT + t) * OUTD;
                o[tid] = xl;
                o[100 + tid] = xs;
            }
        }
        if (tid >= 128 && tid < 168) {
            int u = tid - 128, bb = u / 20, j = u % 20;
            if (j < 10) s_h1[bb][j] = s_h1n[bb][j];
            else        s_h2[bb][j - 10] = s_h2n[bb][j - 10];
        }
        __syncthreads();
    }
}

extern "C" void kernel_launch(void* const* d_in, const int* in_sizes, int n_in,
                              void* d_out, int out_size) {
    const float* x      = (const float*)d_in[0];
    const float* eps    = (const float*)d_in[1];
    const float* W_ih1  = (const float*)d_in[2];
    const float* W_hh1  = (const float*)d_in[3];
    const float* b_ih1  = (const float*)d_in[4];
    const float* b_hh1  = (const float*)d_in[5];
    const float* W_ih2  = (const float*)d_in[6];
    const float* W_hh2  = (const float*)d_in[7];
    const float* b_ih2  = (const float*)d_in[8];
    const float* b_hh2  = (const float*)d_in[9];
    const float* dzW1   = (const float*)d_in[10];
    const float* dzb1   = (const float*)d_in[11];
    const float* dzWloc = (const float*)d_in[12];
    const float* dzbloc = (const float*)d_in[13];
    const float* dzWsc  = (const float*)d_in[14];
    const float* dzbsc  = (const float*)d_in[15];
    const float* dxW1   = (const float*)d_in[16];
    const float* dxb1   = (const float*)d_in[17];
    const float* dxWloc = (const float*)d_in[18];
    const float* dxbloc = (const float*)d_in[19];
    const float* dxWsc  = (const float*)d_in[20];
    const float* dxbsc  = (const float*)d_in[21];
    const float* h1_0   = (const float*)d_in[22];
    const float* h2_0   = (const float*)d_in[23];

    int Btot = in_sizes[0] / (TT * DXc);   // 256
    int grid = Btot / 2;                   // 128 blocks, 2 batch elems each

    arfssm_kernel<<<grid, NTHR>>>(x, eps, W_ih1, W_hh1, b_ih1, b_hh1,
                                  W_ih2, W_hh2, b_ih2, b_hh2,
                                  dzW1, dzb1, dzWloc, dzbloc, dzWsc, dzbsc,
                                  dxW1, dxb1, dxWloc, dxbloc, dxWsc, dxbsc,
                                  h1_0, h2_0, (float*)d_out);
}

// round 6
// speedup vs baseline: 1.0453x; 1.0453x over previous
#include <cuda_runtime.h>
#include <math.h>

#define TT   512
#define DXc  100
#define OUTD 500
#define NTHR 224

// ---------------- packed f32x2 helpers (FFMA2) ----------------
__device__ __forceinline__ unsigned long long pack2(float lo, float hi) {
    unsigned long long u;
    asm("mov.b64 %0,{%1,%2};" : "=l"(u) : "f"(lo), "f"(hi));
    return u;
}
__device__ __forceinline__ unsigned long long ffma2(unsigned long long a,
                                                    unsigned long long b,
                                                    unsigned long long c) {
    unsigned long long d;
    asm("fma.rn.f32x2 %0,%1,%2,%3;" : "=l"(d) : "l"(a), "l"(b), "l"(c));
    return d;
}
__device__ __forceinline__ float red2(unsigned long long u) {
    float lo, hi;
    asm("mov.b64 {%0,%1},%2;" : "=f"(lo), "=f"(hi) : "l"(u));
    return lo + hi;
}

// dot over NP float2-pairs: weights packed in registers, vector in shared
template <int NP>
__device__ __forceinline__ float dot_rw(const unsigned long long* __restrict__ w,
                                        const float* __restrict__ v) {
    const float2* v2 = reinterpret_cast<const float2*>(v);
    unsigned long long a0 = 0ull, a1 = 0ull;
#pragma unroll
    for (int p = 0; p < NP; p += 2) {
        float2 t0 = v2[p];
        a0 = ffma2(w[p], pack2(t0.x, t0.y), a0);
        if (p + 1 < NP) {
            float2 t1 = v2[p + 1];
            a1 = ffma2(w[p + 1], pack2(t1.x, t1.y), a1);
        }
    }
    return red2(a0) + red2(a1);
}

// ---------------- fast activations (MUFU-based, ~1e-7 rel err) ----------------
__device__ __forceinline__ float sigm(float x) {
    return __fdividef(1.0f, 1.0f + __expf(-x));
}
__device__ __forceinline__ float tanh_f(float x) {
    x = fminf(fmaxf(x, -15.0f), 15.0f);
    float e = __expf(2.0f * x);
    return __fdividef(e - 1.0f, e + 1.0f);
}
__device__ __forceinline__ float softplus_f(float x) {
    return fmaxf(x, 0.0f) + __logf(1.0f + __expf(-fabsf(x)));
}

__global__ void __launch_bounds__(NTHR, 1)
arfssm_kernel(const float* __restrict__ x, const float* __restrict__ eps,
              const float* __restrict__ W_ih1, const float* __restrict__ W_hh1,
              const float* __restrict__ b_ih1, const float* __restrict__ b_hh1,
              const float* __restrict__ W_ih2, const float* __restrict__ W_hh2,
              const float* __restrict__ b_ih2, const float* __restrict__ b_hh2,
              const float* __restrict__ dzW1, const float* __restrict__ dzb1,
              const float* __restrict__ dzWloc, const float* __restrict__ dzbloc,
              const float* __restrict__ dzWsc, const float* __restrict__ dzbsc,
              const float* __restrict__ dxW1, const float* __restrict__ dxb1,
              const float* __restrict__ dxWloc, const float* __restrict__ dxbloc,
              const float* __restrict__ dxWsc, const float* __restrict__ dxbsc,
              const float* __restrict__ h1_0, const float* __restrict__ h2_0,
              float* __restrict__ out) {
    // -------- static weights in shared --------
    __shared__ __align__(16) float s_Wih2[30 * DXc];    // 3000
    __shared__ __align__(16) float s_Whh1[300], s_Whh2[300];
    __shared__ float s_bih1[32], s_bih2[32], s_bhh1[32], s_bhh2[32];
    __shared__ __align__(16) float s_dzW1[200];
    __shared__ float s_dzb1[20];
    __shared__ __align__(16) float s_dxW1[400];
    __shared__ float s_dxb1[20];

    // -------- dynamic state --------
    __shared__ __align__(16) float s_x[2][2][DXc];      // ping-pong on t&1
    __shared__ __align__(16) float s_z[2][DXc];
    __shared__ __align__(16) float s_hdz[2][20];
    __shared__ __align__(16) float s_hdx[2][2][20];     // [parity][bb][20]
    __shared__ float s_h1[2][2][10], s_h2[2][2][10];    // [parity][bb][10]
    __shared__ float s_gh1[2][32], s_gh2[2][32];
    __shared__ float s_g1[2][32], s_g2[2][32];

    const int tid = threadIdx.x;
    const int b0  = blockIdx.x * 2;

    // -------- cooperative weight load --------
    for (int i = tid; i < 30 * DXc; i += NTHR) s_Wih2[i] = W_ih2[i];
    for (int i = tid; i < 300; i += NTHR) { s_Whh1[i] = W_hh1[i]; s_Whh2[i] = W_hh2[i]; }
    if (tid < 30) {
        s_bih1[tid] = b_ih1[tid]; s_bih2[tid] = b_ih2[tid];
        s_bhh1[tid] = b_hh1[tid]; s_bhh2[tid] = b_hh2[tid];
    }
    for (int i = tid; i < 200; i += NTHR) s_dzW1[i] = dzW1[i];
    for (int i = tid; i < 400; i += NTHR) s_dxW1[i] = dxW1[i];
    if (tid < 20) { s_dzb1[tid] = dzb1[tid]; s_dxb1[tid] = dxb1[tid]; }
    if (tid < 10) {
        float v1 = h1_0[tid], v2 = h2_0[tid];
        s_h1[0][0][tid] = v1; s_h1[0][1][tid] = v1;
        s_h2[0][0][tid] = v2; s_h2[0][1][tid] = v2;
    }
    // preload s_x parity 0 = x(t=0), parity 1 = x(t=1)
    for (int i = tid; i < 400; i += NTHR) {
        int par = i / 200, r = i % 200, bb = r / 100, k = r % 100;
        s_x[par][bb][k] = x[((size_t)(b0 + bb) * TT + par) * DXc + k];
    }

    // -------- register-resident head weights (tid 0..99) --------
    unsigned long long wzl[10], wzs[10], wxl[10], wxs[10];
    float bzl = 0.f, bzs = 0.f, bxl = 0.f, bxs = 0.f;
    float er[2] = {0.f, 0.f};
    if (tid < 100) {
        const float2* p;
        p = reinterpret_cast<const float2*>(dzWloc + tid * 20);
#pragma unroll
        for (int q = 0; q < 10; q++) { float2 t = p[q]; wzl[q] = pack2(t.x, t.y); }
        p = reinterpret_cast<const float2*>(dzWsc + tid * 20);
#pragma unroll
        for (int q = 0; q < 10; q++) { float2 t = p[q]; wzs[q] = pack2(t.x, t.y); }
        p = reinterpret_cast<const float2*>(dxWloc + tid * 20);
#pragma unroll
        for (int q = 0; q < 10; q++) { float2 t = p[q]; wxl[q] = pack2(t.x, t.y); }
        p = reinterpret_cast<const float2*>(dxWsc + tid * 20);
#pragma unroll
        for (int q = 0; q < 10; q++) { float2 t = p[q]; wxs[q] = pack2(t.x, t.y); }
        bzl = dzbloc[tid]; bzs = dzbsc[tid]; bxl = dxbloc[tid]; bxs = dxbsc[tid];
        // eps(t=0)
#pragma unroll
        for (int bb = 0; bb < 2; bb++)
            er[bb] = eps[((size_t)(b0 + bb) * TT) * DXc + tid];
    }
    // -------- gi1 split-2 weights (tid 160..219 used; warps 5,6) --------
    unsigned long long wa[25];
    int gj = 0, gh = 0;
    if (tid >= 160 && tid < 220) {
        int u = tid - 160;
        gj = u >> 1; gh = u & 1;
        const float2* p = reinterpret_cast<const float2*>(W_ih1 + gj * DXc + gh * 50);
#pragma unroll
        for (int q = 0; q < 25; q++) { float2 t = p[q]; wa[q] = pack2(t.x, t.y); }
    }
    __syncthreads();

    float4 xpre = make_float4(0.f, 0.f, 0.f, 0.f);

    for (int t = 0; t < TT; t++) {
        const int cur = t & 1, nxt = cur ^ 1;

        // ================= Stage A =================
        if (tid < 60) {                      // gh1 + gh2 (bb, j)
            int bb = tid / 30, j = tid % 30;
            float a1 = s_bhh1[j], a2 = s_bhh2[j];
#pragma unroll
            for (int k = 0; k < 10; k++) {
                a1 = fmaf(s_Whh1[j * 10 + k], s_h1[cur][bb][k], a1);
                a2 = fmaf(s_Whh2[j * 10 + k], s_h2[cur][bb][k], a2);
            }
            s_gh1[bb][j] = a1; s_gh2[bb][j] = a2;
        } else if (tid < 100) {              // hdz (bb, j<20)
            int u = tid - 60, bb = u / 20, j = u % 20;
            float a = s_dzb1[j];
#pragma unroll
            for (int k = 0; k < 10; k++) a = fmaf(s_dzW1[j * 10 + k], s_h1[cur][bb][k], a);
            s_hdz[bb][j] = fmaxf(a, 0.0f);
        } else if (tid < 160) {              // gi2 (bb, j<30), weights from shared
            int u = tid - 100, bb = u / 30, j = u % 30;
            const float4* w4 = reinterpret_cast<const float4*>(s_Wih2 + j * DXc);
            const float4* v4 = reinterpret_cast<const float4*>(&s_x[cur][bb][0]);
            unsigned long long a0 = 0ull, a1 = 0ull;
#pragma unroll
            for (int p = 0; p < 25; p++) {
                float4 w = w4[p], v = v4[p];
                a0 = ffma2(pack2(w.x, w.y), pack2(v.x, v.y), a0);
                a1 = ffma2(pack2(w.z, w.w), pack2(v.z, v.w), a1);
            }
            s_g2[bb][j] = s_bih2[j] + red2(a0) + red2(a1);
        } else {                             // x prefetch (t+2), 50 float4 loads
            int i = tid - 160;
            if (t + 2 < TT && i < 50) {
                int bb = i / 25, f = i % 25;
                xpre = *reinterpret_cast<const float4*>(
                    x + ((size_t)(b0 + bb) * TT + t + 2) * DXc + f * 4);
            }
        }
        __syncthreads();

        // ================= Stage B =================
        if (tid < 100) {                     // z-head
#pragma unroll
            for (int bb = 0; bb < 2; bb++) {
                float zl = dot_rw<10>(wzl, &s_hdz[bb][0]) + bzl;
                float zs = softplus_f(dot_rw<10>(wzs, &s_hdz[bb][0]) + bzs);
                float zt = fmaf(zs, er[bb], zl);
                s_z[bb][tid] = zt;
                float* o = out + ((size_t)(b0 + bb) * TT + t) * OUTD;
                o[200 + tid] = zl;
                o[300 + tid] = zs;
                o[400 + tid] = zt;
            }
            if (t + 1 < TT) {                // eps prefetch (t+1)
#pragma unroll
                for (int bb = 0; bb < 2; bb++)
                    er[bb] = eps[((size_t)(b0 + bb) * TT + t + 1) * DXc + tid];
            }
        } else if (tid < 120) {              // GRU2 combine -> h2[nxt]
            int u = tid - 100, bb = u / 10, j = u % 10;
            float r  = sigm(s_g2[bb][j] + s_gh2[bb][j]);
            float uu = sigm(s_g2[bb][10 + j] + s_gh2[bb][10 + j]);
            float n  = tanh_f(fmaf(r, s_gh2[bb][20 + j], s_g2[bb][20 + j]));
            s_h2[nxt][bb][j] = fmaf(uu, s_h2[cur][bb][j] - n, n);
        }
        __syncthreads();

        // ================= Stage C =================
        if (tid >= 160) {                    // warps 5,6: gi1 -> GRU1 -> hdx
            int u = tid - 160;
            int lane = tid & 31;
            int w = (tid >> 5) - 5;          // 0 or 1 (= batch for hdx role)
            // C1: gi1 split-2 over K=100 (60 lanes, both batches)
            if (u < 60) {
                unsigned mask = (tid < 192) ? 0xFFFFFFFFu : 0x0FFFFFFFu;
#pragma unroll
                for (int bb = 0; bb < 2; bb++) {
                    float v = dot_rw<25>(wa, &s_z[bb][gh * 50]);
                    v += __shfl_xor_sync(mask, v, 1);
                    if (gh == 0) s_g1[bb][gj] = v + s_bih1[gj];
                }
            }
            asm volatile("bar.sync 1, 64;" ::: "memory");
            // C2: GRU1 combine (redundant in both warps) + in-warp hdx
            float h1n = 0.0f;
            if (lane < 20) {
                int bb = lane / 10, j = lane % 10;
                float r  = sigm(s_g1[bb][j] + s_gh1[bb][j]);
                float uu = sigm(s_g1[bb][10 + j] + s_gh1[bb][10 + j]);
                float n  = tanh_f(fmaf(r, s_gh1[bb][20 + j], s_g1[bb][20 + j]));
                h1n = fmaf(uu, s_h1[cur][bb][j] - n, n);
                if (w == 0) s_h1[nxt][bb][j] = h1n;
            }
            // broadcast own-batch h1n (lanes w*10 .. w*10+9 hold it)
            float hk[10];
#pragma unroll
            for (int k = 0; k < 10; k++)
                hk[k] = __shfl_sync(0xFFFFFFFFu, h1n, w * 10 + k);
            if (lane < 20) {                 // hdx[w][lane]
                float acc = s_dxb1[lane];
#pragma unroll
                for (int k = 0; k < 10; k++) acc = fmaf(s_dxW1[lane * 20 + k], hk[k], acc);
#pragma unroll
                for (int k = 0; k < 10; k++) acc = fmaf(s_dxW1[lane * 20 + 10 + k], s_h2[cur][w][k], acc);
                s_hdx[cur][w][lane] = fmaxf(acc, 0.0f);
            }
            // stash prefetched x(t+2) into s_x[cur] (read next at stage A of t+2)
            if (t + 2 < TT && u < 50) {
                reinterpret_cast<float4*>(&s_x[cur][u / 25][0])[u % 25] = xpre;
            }
        }
        if (tid < 100 && t > 0) {            // x-head for step t-1 (pipelined)
            int prev = (t - 1) & 1;
#pragma unroll
            for (int bb = 0; bb < 2; bb++) {
                float xl = dot_rw<10>(wxl, &s_hdx[prev][bb][0]) + bxl;
                float xs = softplus_f(dot_rw<10>(wxs, &s_hdx[prev][bb][0]) + bxs);
                float* o = out + ((size_t)(b0 + bb) * TT + (t - 1)) * OUTD;
                o[tid] = xl;
                o[100 + tid] = xs;
            }
        }
        __syncthreads();
    }

    // epilogue: x-head for t = TT-1
    if (tid < 100) {
        int prev = (TT - 1) & 1;
#pragma unroll
        for (int bb = 0; bb < 2; bb++) {
            float xl = dot_rw<10>(wxl, &s_hdx[prev][bb][0]) + bxl;
            float xs = softplus_f(dot_rw<10>(wxs, &s_hdx[prev][bb][0]) + bxs);
            float* o = out + ((size_t)(b0 + bb) * TT + (TT - 1)) * OUTD;
            o[tid] = xl;
            o[100 + tid] = xs;
        }
    }
}

extern "C" void kernel_launch(void* const* d_in, const int* in_sizes, int n_in,
                              void* d_out, int out_size) {
    const float* x      = (const float*)d_in[0];
    const float* eps    = (const float*)d_in[1];
    const float* W_ih1  = (const float*)d_in[2];
    const float* W_hh1  = (const float*)d_in[3];
    const float* b_ih1  = (const float*)d_in[4];
    const float* b_hh1  = (const float*)d_in[5];
    const float* W_ih2  = (const float*)d_in[6];
    const float* W_hh2  = (const float*)d_in[7];
    const float* b_ih2  = (const float*)d_in[8];
    const float* b_hh2  = (const float*)d_in[9];
    const float* dzW1   = (const float*)d_in[10];
    const float* dzb1   = (const float*)d_in[11];
    const float* dzWloc = (const float*)d_in[12];
    const float* dzbloc = (const float*)d_in[13];
    const float* dzWsc  = (const float*)d_in[14];
    const float* dzbsc  = (const float*)d_in[15];
    const float* dxW1   = (const float*)d_in[16];
    const float* dxb1   = (const float*)d_in[17];
    const float* dxWloc = (const float*)d_in[18];
    const float* dxbloc = (const float*)d_in[19];
    const float* dxWsc  = (const float*)d_in[20];
    const float* dxbsc  = (const float*)d_in[21];
    const float* h1_0   = (const float*)d_in[22];
    const float* h2_0   = (const float*)d_in[23];

    int Btot = in_sizes[0] / (TT * DXc);   // 256
    int grid = Btot / 2;                   // 128 blocks, 2 batch elems each

    arfssm_kernel<<<grid, NTHR>>>(x, eps, W_ih1, W_hh1, b_ih1, b_hh1,
                                  W_ih2, W_hh2, b_ih2, b_hh2,
                                  dzW1, dzb1, dzWloc, dzbloc, dzWsc, dzbsc,
                                  dxW1, dxb1, dxWloc, dxbloc, dxWsc, dxbsc,
                                  h1_0, h2_0, (float*)d_out);
}